// round 5
// baseline (speedup 1.0000x reference)
#include <cuda_runtime.h>
#include <cuda_bf16.h>

#define D 64
#define MAXN 100032
#define MAXE 1600000
#define NEG_SLOPE 0.2f

// ---------------- scratch (static device memory; no allocs allowed) -------------
__device__ float g_P[64 * 128];   // P[r][0:64]=W_top@rel_r, [64:128]=W_bot@rel_r
__device__ int   g_is64;          // 1 if edge arrays are int64, 0 if int32
__device__ int   g_deg[MAXN];
__device__ int   g_ptr[MAXN + 1];
__device__ int   g_cur[MAXN];
__device__ int   g_bsum[256];
__device__ int   g_packed[MAXE];  // (rel<<20) | tail
__device__ float g_embA[MAXN * D];
__device__ float g_embB[MAXN * D];

// ---------------- helpers ----------------
__device__ __forceinline__ float warp_sum(float v) {
    v += __shfl_xor_sync(0xffffffffu, v, 16);
    v += __shfl_xor_sync(0xffffffffu, v, 8);
    v += __shfl_xor_sync(0xffffffffu, v, 4);
    v += __shfl_xor_sync(0xffffffffu, v, 2);
    v += __shfl_xor_sync(0xffffffffu, v, 1);
    return v;
}

__device__ __forceinline__ int load_idx(const void* base, long long i, int is64) {
    if (is64) return (int)((const long long*)base)[i];
    return ((const int*)base)[i];
}

// ---------------- dtype detection: int64 little-endian values < 2^32 have all
// odd 32-bit words zero; int32 head values in [0,1e5) make that impossible. ----
__global__ void k_detect(const unsigned int* __restrict__ w) {
    if (threadIdx.x == 0) {
        int all0 = 1;
        for (int i = 0; i < 128; i++)
            if (w[2 * i + 1] != 0u) { all0 = 0; break; }
        g_is64 = all0;
    }
}

// ---------------- precompute P[r][j] = sum_d W[j][d] * rel[r][d] ----------------
__global__ void k_precompute_P(const float* __restrict__ W,
                               const float* __restrict__ rel) {
    int r = blockIdx.x;      // 0..R-1
    int j = threadIdx.x;     // 0..127
    const float* wrow = W + j * D;
    const float* rrow = rel + r * D;
    float s = 0.f;
#pragma unroll
    for (int d = 0; d < D; d++) s += wrow[d] * rrow[d];
    g_P[r * 128 + j] = s;
}

// ---------------- CSR build ----------------
__global__ void k_hist(const void* __restrict__ ei, int E) {
    int e = blockIdx.x * blockDim.x + threadIdx.x;
    if (e >= E) return;
    int head = load_idx(ei, e, g_is64);
    atomicAdd(&g_deg[head], 1);
}

__global__ void k_scan1(int n) {
    __shared__ int sh[1024];
    int i = blockIdx.x * 1024 + threadIdx.x;
    int v = (i < n) ? g_deg[i] : 0;
    sh[threadIdx.x] = v;
    __syncthreads();
#pragma unroll
    for (int off = 1; off < 1024; off <<= 1) {
        int t = (threadIdx.x >= off) ? sh[threadIdx.x - off] : 0;
        __syncthreads();
        sh[threadIdx.x] += t;
        __syncthreads();
    }
    if (i < n) g_ptr[i] = sh[threadIdx.x] - v;   // exclusive
    if (threadIdx.x == 1023) g_bsum[blockIdx.x] = sh[1023];
}

__global__ void k_scan2(int nb) {
    if (threadIdx.x == 0) {
        int acc = 0;
        for (int b = 0; b < nb; b++) {
            int t = g_bsum[b];
            g_bsum[b] = acc;
            acc += t;
        }
    }
}

__global__ void k_scan3(int n, int E) {
    int i = blockIdx.x * 1024 + threadIdx.x;
    if (i < n) {
        int p = g_ptr[i] + g_bsum[blockIdx.x];
        g_ptr[i] = p;
        g_cur[i] = p;
    }
    if (i == 0) g_ptr[n] = E;
}

__global__ void k_place(const void* __restrict__ ei,
                        const void* __restrict__ et, int E) {
    int e = blockIdx.x * blockDim.x + threadIdx.x;
    if (e >= E) return;
    int is64 = g_is64;
    int head = load_idx(ei, e, is64);
    int tail = load_idx(ei, (long long)E + e, is64);
    int rt   = load_idx(et, e, is64);
    int pos = atomicAdd(&g_cur[head], 1);
    g_packed[pos] = (rt << 20) | tail;
}

// ---------------- one hop: warp per head node, register-resident softmax+agg ----
__global__ __launch_bounds__(256)
void k_hop(const float* __restrict__ ein, float* __restrict__ eout,
           float* __restrict__ res, int N) {
    int warp = (blockIdx.x * blockDim.x + threadIdx.x) >> 5;
    int lane = threadIdx.x & 31;
    if (warp >= N) return;

    const float2 eh = *(const float2*)(ein + warp * D + 2 * lane);
    int start = g_ptr[warp];
    int end   = g_ptr[warp + 1];

    float  s   = 0.f;
    float2 acc = make_float2(0.f, 0.f);

    for (int e = start; e < end; e++) {
        int pk   = g_packed[e];
        int tail = pk & 0xFFFFF;
        int rt   = pk >> 20;
        const float2 et = *(const float2*)(ein + tail * D + 2 * lane);
        const float2 pt = *(const float2*)(g_P + rt * 128 + 2 * lane);
        const float2 pb = *(const float2*)(g_P + rt * 128 + 64 + 2 * lane);
        float part = eh.x * pt.x + eh.y * pt.y + et.x * pb.x + et.y * pb.y;
        float logit = warp_sum(part);
        logit = (logit > 0.f) ? logit : NEG_SLOPE * logit;
        float w = __expf(logit);   // max-subtraction dropped: exactly equivalent
        s += w;
        acc.x += w * et.x;
        acc.y += w * et.y;
    }

    float2 v;
    if (end > start) {
        float inv = 1.f / s;
        v.x = eh.x + acc.x * inv;
        v.y = eh.y + acc.y * inv;
    } else {
        v = eh;                    // agg = 0 for nodes with no out-edges
    }

    // row-wise L2 normalize
    float nrm2 = warp_sum(v.x * v.x + v.y * v.y);
    float nrm  = fmaxf(sqrtf(nrm2), 1e-12f);
    float inv_n = 1.f / nrm;
    v.x *= inv_n;
    v.y *= inv_n;

    *(float2*)(eout + warp * D + 2 * lane) = v;

    float2 r = *(float2*)(res + warp * D + 2 * lane);
    r.x = 0.5f * r.x + v.x;
    r.y = 0.5f * r.y + v.y;
    *(float2*)(res + warp * D + 2 * lane) = r;
}

// ---------------- launch ----------------
extern "C" void kernel_launch(void* const* d_in, const int* in_sizes, int n_in,
                              void* d_out, int out_size) {
    const void*  ei  = d_in[0];                  // [2, E] int32 or int64
    const void*  et  = d_in[1];                  // [E]    int32 or int64
    const float* ent = (const float*)d_in[2];    // [N, 64]
    const float* rel = (const float*)d_in[3];    // [R, 64]
    const float* W   = (const float*)d_in[4];    // [128, 64]
    float*       res = (float*)d_out;            // [N, 64]

    int E = in_sizes[0] / 2;
    int N = in_sizes[2] / D;
    int R = in_sizes[3] / D;

    void *p_deg, *p_embA, *p_embB;
    cudaGetSymbolAddress(&p_deg,  g_deg);
    cudaGetSymbolAddress(&p_embA, g_embA);
    cudaGetSymbolAddress(&p_embB, g_embB);

    cudaMemsetAsync(p_deg, 0, (size_t)N * sizeof(int), 0);

    // dtype detection must precede any use of edge arrays
    k_detect<<<1, 32>>>((const unsigned int*)ei);

    // P precompute
    k_precompute_P<<<R, 128>>>(W, rel);

    // CSR build
    int egrid = (E + 255) / 256;
    k_hist<<<egrid, 256>>>(ei, E);
    int nblk = (N + 1023) / 1024;
    k_scan1<<<nblk, 1024>>>(N);
    k_scan2<<<1, 32>>>(nblk);
    k_scan3<<<nblk, 1024>>>(N, E);
    k_place<<<egrid, 256>>>(ei, et, E);

    // init emb = entity_emb, res = entity_emb
    cudaMemcpyAsync(p_embA, ent, (size_t)N * D * sizeof(float),
                    cudaMemcpyDeviceToDevice, 0);
    cudaMemcpyAsync(res, ent, (size_t)N * D * sizeof(float),
                    cudaMemcpyDeviceToDevice, 0);

    // two hops, ping-pong emb buffers, res updated in-place (d_out)
    int hgrid = (N * 32 + 255) / 256;
    k_hop<<<hgrid, 256>>>((float*)p_embA, (float*)p_embB, res, N);
    k_hop<<<hgrid, 256>>>((float*)p_embB, (float*)p_embA, res, N);
}

// round 8
// speedup vs baseline: 1.1629x; 1.1629x over previous
#include <cuda_runtime.h>
#include <cuda_bf16.h>

#define D 64
#define MAXN 100032
#define MAXE 1600000
#define NEG_SLOPE 0.2f

// ---------------- scratch (static device memory; no allocs allowed) -------------
__device__ float4 g_Q[64 * 32];   // Q[r][l] = (Pt[2l], Pt[2l+1], Pb[2l], Pb[2l+1])
__device__ int   g_is64;          // 1 if edge arrays are int64, 0 if int32
__device__ int   g_deg[MAXN];
__device__ int   g_ptr[MAXN + 1];
__device__ int   g_cur[MAXN];
__device__ int   g_bsum[256];
__device__ int   g_packed[MAXE];  // (rel<<20) | tail
__device__ float g_embA[MAXN * D];

// ---------------- helpers ----------------
__device__ __forceinline__ float warp_sum(float v) {
    v += __shfl_xor_sync(0xffffffffu, v, 16);
    v += __shfl_xor_sync(0xffffffffu, v, 8);
    v += __shfl_xor_sync(0xffffffffu, v, 4);
    v += __shfl_xor_sync(0xffffffffu, v, 2);
    v += __shfl_xor_sync(0xffffffffu, v, 1);
    return v;
}

__device__ __forceinline__ int load_idx(const void* base, long long i, int is64) {
    if (is64) return (int)((const long long*)base)[i];
    return ((const int*)base)[i];
}

// ---------------- dtype detection (warp-parallel): int64 LE values < 2^32 have
// all odd 32-bit words zero; int32 head values make that essentially impossible.
__global__ void k_detect(const unsigned int* __restrict__ w) {
    int lane = threadIdx.x;
    // check odd words of first 64 presumed-int64 entries, two per lane
    unsigned int a = w[2 * lane + 1];
    unsigned int b = w[2 * (lane + 32) + 1];
    unsigned int nz = __ballot_sync(0xffffffffu, (a | b) != 0u);
    if (lane == 0) g_is64 = (nz == 0u) ? 1 : 0;
}

// ---------------- precompute P and pack to float4 table --------------------------
__global__ void k_precompute_P(const float* __restrict__ W,
                               const float* __restrict__ rel) {
    int r = blockIdx.x;      // 0..R-1
    int j = threadIdx.x;     // 0..127 : row of W
    const float* wrow = W + j * D;
    const float* rrow = rel + r * D;
    float s = 0.f;
#pragma unroll
    for (int d = 0; d < D; d++) s += wrow[d] * rrow[d];
    // pack: j<64 -> top half (components x,y), j>=64 -> bottom half (z,w)
    int jj   = (j < 64) ? j : (j - 64);
    int lane = jj >> 1;
    int comp = (jj & 1) + ((j < 64) ? 0 : 2);
    ((float*)&g_Q[r * 32 + lane])[comp] = s;
}

// ---------------- CSR build ----------------
__global__ void k_hist(const void* __restrict__ ei, int E) {
    int e = blockIdx.x * blockDim.x + threadIdx.x;
    if (e >= E) return;
    int head = load_idx(ei, e, g_is64);
    atomicAdd(&g_deg[head], 1);
}

__global__ void k_scan1(int n) {
    __shared__ int sh[1024];
    int i = blockIdx.x * 1024 + threadIdx.x;
    int v = (i < n) ? g_deg[i] : 0;
    sh[threadIdx.x] = v;
    __syncthreads();
#pragma unroll
    for (int off = 1; off < 1024; off <<= 1) {
        int t = (threadIdx.x >= off) ? sh[threadIdx.x - off] : 0;
        __syncthreads();
        sh[threadIdx.x] += t;
        __syncthreads();
    }
    if (i < n) g_ptr[i] = sh[threadIdx.x] - v;   // exclusive
    if (threadIdx.x == 1023) g_bsum[blockIdx.x] = sh[1023];
}

__global__ void k_scan2(int nb) {
    if (threadIdx.x == 0) {
        int acc = 0;
        for (int b = 0; b < nb; b++) {
            int t = g_bsum[b];
            g_bsum[b] = acc;
            acc += t;
        }
    }
}

__global__ void k_scan3(int n, int E) {
    int i = blockIdx.x * 1024 + threadIdx.x;
    if (i < n) {
        int p = g_ptr[i] + g_bsum[blockIdx.x];
        g_ptr[i] = p;
        g_cur[i] = p;
    }
    if (i == 0) g_ptr[n] = E;
}

__global__ void k_place(const void* __restrict__ ei,
                        const void* __restrict__ et, int E) {
    int e = blockIdx.x * blockDim.x + threadIdx.x;
    if (e >= E) return;
    int is64 = g_is64;
    int head = load_idx(ei, e, is64);
    int tail = load_idx(ei, (long long)E + e, is64);
    int rt   = load_idx(et, e, is64);
    int pos = atomicAdd(&g_cur[head], 1);
    g_packed[pos] = (rt << 20) | tail;
}

// ---------------- one hop: warp per head node, register-resident softmax+agg ----
// FINAL=0: eout[n] = normalized hop output.
// FINAL=1: eout[n] = 0.25*ent[n] + 0.5*ein[n] + normalized hop output  (= res)
template <int FINAL>
__global__ __launch_bounds__(256)
void k_hop(const float* __restrict__ ein, float* __restrict__ eout,
           const float* __restrict__ ent, int N) {
    int warp = (blockIdx.x * blockDim.x + threadIdx.x) >> 5;
    int lane = threadIdx.x & 31;
    if (warp >= N) return;

    const float2 eh = *(const float2*)(ein + warp * D + 2 * lane);
    int start = g_ptr[warp];
    int end   = g_ptr[warp + 1];

    float  s   = 0.f;
    float2 acc = make_float2(0.f, 0.f);

    for (int base = start; base < end; base += 32) {
        int cnt = end - base;
        if (cnt > 32) cnt = 32;
        int pk_l = (lane < cnt) ? g_packed[base + lane] : 0;
        for (int j = 0; j < cnt; j++) {
            int pk   = __shfl_sync(0xffffffffu, pk_l, j);
            int tail = pk & 0xFFFFF;
            int rt   = pk >> 20;
            const float2 et = *(const float2*)(ein + tail * D + 2 * lane);
            const float4 q  = g_Q[rt * 32 + lane];
            float part = eh.x * q.x + eh.y * q.y + et.x * q.z + et.y * q.w;
            float logit = warp_sum(part);
            logit = (logit > 0.f) ? logit : NEG_SLOPE * logit;
            float w = __expf(logit);   // max-subtraction dropped: exactly equivalent
            s += w;
            acc.x += w * et.x;
            acc.y += w * et.y;
        }
    }

    float2 v;
    if (end > start) {
        float inv = 1.f / s;
        v.x = eh.x + acc.x * inv;
        v.y = eh.y + acc.y * inv;
    } else {
        v = eh;                    // agg = 0 for nodes with no out-edges
    }

    // row-wise L2 normalize
    float nrm2 = warp_sum(v.x * v.x + v.y * v.y);
    float nrm  = fmaxf(sqrtf(nrm2), 1e-12f);
    float inv_n = 1.f / nrm;
    v.x *= inv_n;
    v.y *= inv_n;

    if (FINAL) {
        const float2 e0 = *(const float2*)(ent + warp * D + 2 * lane);
        v.x = 0.25f * e0.x + 0.5f * eh.x + v.x;
        v.y = 0.25f * e0.y + 0.5f * eh.y + v.y;
    }
    *(float2*)(eout + warp * D + 2 * lane) = v;
}

// ---------------- launch ----------------
extern "C" void kernel_launch(void* const* d_in, const int* in_sizes, int n_in,
                              void* d_out, int out_size) {
    const void*  ei  = d_in[0];                  // [2, E] int32 or int64
    const void*  et  = d_in[1];                  // [E]    int32 or int64
    const float* ent = (const float*)d_in[2];    // [N, 64]
    const float* rel = (const float*)d_in[3];    // [R, 64]
    const float* W   = (const float*)d_in[4];    // [128, 64]
    float*       res = (float*)d_out;            // [N, 64]

    int E = in_sizes[0] / 2;
    int N = in_sizes[2] / D;
    int R = in_sizes[3] / D;

    void *p_deg, *p_embA;
    cudaGetSymbolAddress(&p_deg,  g_deg);
    cudaGetSymbolAddress(&p_embA, g_embA);

    cudaMemsetAsync(p_deg, 0, (size_t)N * sizeof(int), 0);

    // dtype detection must precede any use of edge arrays
    k_detect<<<1, 32>>>((const unsigned int*)ei);

    // P precompute (packed float4 table)
    k_precompute_P<<<R, 128>>>(W, rel);

    // CSR build
    int egrid = (E + 255) / 256;
    k_hist<<<egrid, 256>>>(ei, E);
    int nblk = (N + 1023) / 1024;
    k_scan1<<<nblk, 1024>>>(N);
    k_scan2<<<1, 32>>>(nblk);
    k_scan3<<<nblk, 1024>>>(N, E);
    k_place<<<egrid, 256>>>(ei, et, E);

    // hop 1: ent -> g_embA ; hop 2: g_embA -> res (with fused residual)
    int hgrid = (N + 7) / 8;   // 8 warps per 256-thread block
    k_hop<0><<<hgrid, 256>>>(ent, (float*)p_embA, ent, N);
    k_hop<1><<<hgrid, 256>>>((float*)p_embA, res, ent, N);
}